// round 1
// baseline (speedup 1.0000x reference)
#include <cuda_runtime.h>
#include <math.h>
#include <stdint.h>

#define NODES  100000
#define DIM    512
#define BPAIRS 2048
#define ROWS   4096          // [l_emb(2048) ; r_emb(2048)]
#define GAMMA_ 3.0f
#define LAMB_  20.0f
#define TAU_   8.0f

// ---------------- scratch (static __device__: no allocs allowed) -------------
__device__ float g_A[(size_t)ROWS * DIM];            // gathered queries, 8 MB
__device__ float g_asq[ROWS];
__device__ float g_pos[BPAIRS];
__device__ float g_esq[NODES];
__device__ float g_loss[(size_t)ROWS * NODES];       // 1.638 GB fp32
__device__ float g_sum[ROWS];
__device__ float g_sumsq[ROWS];
__device__ float g_max[ROWS];
__device__ float g_sumexp[ROWS];

__device__ __forceinline__ void atomicMaxFloat(float* addr, float v) {
    int* ai = (int*)addr;
    int old = *ai;
    while (__int_as_float(old) < v) {
        int prev = atomicCAS(ai, old, __float_as_int(v));
        if (prev == old) break;
        old = prev;
    }
}

// ---------------- init ------------------------------------------------------
__global__ void k_init() {
    int i = blockIdx.x * blockDim.x + threadIdx.x;
    if (i < ROWS) {
        g_sum[i] = 0.f; g_sumsq[i] = 0.f; g_sumexp[i] = 0.f;
        g_max[i] = -INFINITY;
    }
}

// ---------------- emb_sq: one warp per node ---------------------------------
__global__ void k_esq(const float* __restrict__ emb) {
    int node = blockIdx.x * 8 + (threadIdx.x >> 5);
    if (node >= NODES) return;
    int lane = threadIdx.x & 31;
    const float4* p = (const float4*)(emb + (size_t)node * DIM);
    float s = 0.f;
    #pragma unroll
    for (int i = lane; i < DIM / 4; i += 32) {
        float4 v = p[i];
        s += v.x * v.x + v.y * v.y + v.z * v.z + v.w * v.w;
    }
    #pragma unroll
    for (int o = 16; o; o >>= 1) s += __shfl_xor_sync(0xffffffffu, s, o);
    if (lane == 0) g_esq[node] = s;
}

// ---------------- gather A rows + a_sq: one warp per row --------------------
__global__ void k_gather(const int* __restrict__ pairs, const float* __restrict__ emb) {
    int row = blockIdx.x * 8 + (threadIdx.x >> 5);
    if (row >= ROWS) return;
    int lane = threadIdx.x & 31;
    int p    = row & (BPAIRS - 1);
    int side = row >> 11;                 // 0 for rows<2048 (l), 1 otherwise (r)
    int node = pairs[2 * p + side];
    const float4* src = (const float4*)(emb + (size_t)node * DIM);
    float4*       dst = (float4*)(g_A + (size_t)row * DIM);
    float s = 0.f;
    #pragma unroll
    for (int i = lane; i < DIM / 4; i += 32) {
        float4 v = src[i];
        dst[i] = v;
        s += v.x * v.x + v.y * v.y + v.z * v.z + v.w * v.w;
    }
    #pragma unroll
    for (int o = 16; o; o >>= 1) s += __shfl_xor_sync(0xffffffffu, s, o);
    if (lane == 0) g_asq[row] = s;
}

// ---------------- pos_dis: one warp per pair --------------------------------
__global__ void k_pos() {
    int p = blockIdx.x * 8 + (threadIdx.x >> 5);
    if (p >= BPAIRS) return;
    int lane = threadIdx.x & 31;
    const float4* a = (const float4*)(g_A + (size_t)p * DIM);
    const float4* b = (const float4*)(g_A + (size_t)(p + BPAIRS) * DIM);
    float s = 0.f;
    #pragma unroll
    for (int i = lane; i < DIM / 4; i += 32) {
        float4 x = a[i], y = b[i];
        float dx = x.x - y.x, dy = x.y - y.y, dz = x.z - y.z, dw = x.w - y.w;
        s += dx * dx + dy * dy + dz * dz + dw * dw;
    }
    #pragma unroll
    for (int o = 16; o; o >>= 1) s += __shfl_xor_sync(0xffffffffu, s, o);
    if (lane == 0) g_pos[p] = s;
}

// ---------------- GEMM + loss + per-row stats -------------------------------
// Tile: BM=128 x BN=128 x BK=16, 256 threads (16x16), 8x8 microtile.
#define BM 128
#define BN 128
#define BK 16

__global__ void __launch_bounds__(256, 2) k_gemm(const float* __restrict__ E,
                                                 const int* __restrict__ pairs) {
    __shared__ float As[BK][BM];
    __shared__ float Bs[BK][BN + 4];
    __shared__ float s_asq[BM];
    __shared__ float s_pos[BM];
    __shared__ int   s_l[BM], s_r[BM];

    const int tid = threadIdx.x;
    const int m0  = blockIdx.x * BM;     // row tile (gridDim.x = 32)
    const int n0  = blockIdx.y * BN;     // node tile (gridDim.y = 782)

    if (tid < BM) {
        int row = m0 + tid;
        s_asq[tid] = g_asq[row];
        int p = row & (BPAIRS - 1);
        s_pos[tid] = g_pos[p];
        s_l[tid] = pairs[2 * p];
        s_r[tid] = pairs[2 * p + 1];
    }

    float acc[8][8];
    #pragma unroll
    for (int i = 0; i < 8; i++)
        #pragma unroll
        for (int j = 0; j < 8; j++) acc[i][j] = 0.f;

    const int ty = tid >> 4, tx = tid & 15;

    for (int k0 = 0; k0 < DIM; k0 += BK) {
        // A tile: 128 rows x 16 k  (512 float4, 2 per thread)
        #pragma unroll
        for (int it = 0; it < 2; it++) {
            int idx = tid + 256 * it;
            int r = idx >> 2, c4 = idx & 3;
            float4 v = *(const float4*)(g_A + (size_t)(m0 + r) * DIM + k0 + c4 * 4);
            As[c4 * 4 + 0][r] = v.x; As[c4 * 4 + 1][r] = v.y;
            As[c4 * 4 + 2][r] = v.z; As[c4 * 4 + 3][r] = v.w;
        }
        // B tile: 128 nodes x 16 k
        #pragma unroll
        for (int it = 0; it < 2; it++) {
            int idx = tid + 256 * it;
            int c = idx >> 2, c4 = idx & 3;
            int node = n0 + c;
            float4 v = make_float4(0.f, 0.f, 0.f, 0.f);
            if (node < NODES)
                v = *(const float4*)(E + (size_t)node * DIM + k0 + c4 * 4);
            Bs[c4 * 4 + 0][c] = v.x; Bs[c4 * 4 + 1][c] = v.y;
            Bs[c4 * 4 + 2][c] = v.z; Bs[c4 * 4 + 3][c] = v.w;
        }
        __syncthreads();

        #pragma unroll
        for (int k = 0; k < BK; k++) {
            float4 a0 = *(const float4*)&As[k][ty * 8];
            float4 a1 = *(const float4*)&As[k][ty * 8 + 4];
            float4 b0 = *(const float4*)&Bs[k][tx * 8];
            float4 b1 = *(const float4*)&Bs[k][tx * 8 + 4];
            float ra[8] = {a0.x, a0.y, a0.z, a0.w, a1.x, a1.y, a1.z, a1.w};
            float rb[8] = {b0.x, b0.y, b0.z, b0.w, b1.x, b1.y, b1.z, b1.w};
            #pragma unroll
            for (int i = 0; i < 8; i++)
                #pragma unroll
                for (int j = 0; j < 8; j++) acc[i][j] += ra[i] * rb[j];
        }
        __syncthreads();
    }

    // epilogue: loss, store, per-row partial stats
    float ecol[8];
    #pragma unroll
    for (int j = 0; j < 8; j++) {
        int col = n0 + tx * 8 + j;
        ecol[j] = (col < NODES) ? __ldg(&g_esq[col]) : 0.f;
    }

    #pragma unroll
    for (int i = 0; i < 8; i++) {
        int mr  = ty * 8 + i;
        int row = m0 + mr;
        float asq = s_asq[mr], pos = s_pos[mr];
        int   li = s_l[mr], ri = s_r[mr];
        float psum = 0.f, psq = 0.f, pmax = -INFINITY;
        #pragma unroll
        for (int j = 0; j < 8; j++) {
            int col = n0 + tx * 8 + j;
            if (col < NODES) {
                float dot  = acc[i][j];
                float neg  = asq + ecol[j] - 2.f * dot;
                float mask = 1.f - (col == li ? 1.f : 0.f) - (col == ri ? 1.f : 0.f);
                float loss = (pos - neg + GAMMA_) * mask;
                g_loss[(size_t)row * NODES + col] = loss;
                psum += loss;
                psq  += loss * loss;
                pmax  = fmaxf(pmax, loss);
            }
        }
        // reduce over the 16 tx lanes (xor<16 stays within each half-warp)
        #pragma unroll
        for (int o = 8; o; o >>= 1) {
            psum += __shfl_xor_sync(0xffffffffu, psum, o);
            psq  += __shfl_xor_sync(0xffffffffu, psq, o);
            pmax  = fmaxf(pmax, __shfl_xor_sync(0xffffffffu, pmax, o));
        }
        if (tx == 0) {
            atomicAdd(&g_sum[row], psum);
            atomicAdd(&g_sumsq[row], psq);
            atomicMaxFloat(&g_max[row], pmax);
        }
    }
}

// ---------------- pass 2: sum of exp(scale*(x - max)) -----------------------
// grid: (25 chunks of 1000 float4, 4096 rows)
__global__ void __launch_bounds__(256) k_pass2() {
    const int row = blockIdx.y;
    float mu  = g_sum[row] * (1.f / NODES);
    float var = g_sumsq[row] * (1.f / NODES) - mu * mu;
    float sd  = sqrtf(fmaxf(var, 0.f));
    float scale = LAMB_ / sd;
    float mx  = g_max[row];

    const float4* L = (const float4*)(g_loss + (size_t)row * NODES);
    int start = blockIdx.x * 1000;
    float s = 0.f;
    for (int j = start + threadIdx.x; j < start + 1000; j += 256) {
        float4 v = L[j];
        s += __expf(scale * (v.x - mx));
        s += __expf(scale * (v.y - mx));
        s += __expf(scale * (v.z - mx));
        s += __expf(scale * (v.w - mx));
    }
    __shared__ float red[8];
    int lane = threadIdx.x & 31, wid = threadIdx.x >> 5;
    #pragma unroll
    for (int o = 16; o; o >>= 1) s += __shfl_xor_sync(0xffffffffu, s, o);
    if (lane == 0) red[wid] = s;
    __syncthreads();
    if (threadIdx.x < 8) {
        float v = red[threadIdx.x];
        #pragma unroll
        for (int o = 4; o; o >>= 1) v += __shfl_xor_sync(0xffu, v, o);
        if (threadIdx.x == 0) atomicAdd(&g_sumexp[row], v);
    }
}

// ---------------- finalize: mean over pairs of (lse_l + lse_r) --------------
__global__ void k_final(float* __restrict__ out) {
    __shared__ float red[32];
    float t = 0.f;
    for (int row = threadIdx.x; row < ROWS; row += 1024) {
        float mu  = g_sum[row] * (1.f / NODES);
        float var = g_sumsq[row] * (1.f / NODES) - mu * mu;
        float sd  = sqrtf(fmaxf(var, 0.f));
        float lse = LAMB_ * (g_max[row] - mu) / sd + TAU_ + logf(g_sumexp[row]);
        t += lse;
    }
    int lane = threadIdx.x & 31, wid = threadIdx.x >> 5;
    #pragma unroll
    for (int o = 16; o; o >>= 1) t += __shfl_xor_sync(0xffffffffu, t, o);
    if (lane == 0) red[wid] = t;
    __syncthreads();
    if (threadIdx.x < 32) {
        float v = red[threadIdx.x];
        #pragma unroll
        for (int o = 16; o; o >>= 1) v += __shfl_xor_sync(0xffffffffu, v, o);
        if (threadIdx.x == 0) out[0] = v * (1.f / BPAIRS);
    }
}

// ---------------- launch ----------------------------------------------------
extern "C" void kernel_launch(void* const* d_in, const int* in_sizes, int n_in,
                              void* d_out, int out_size) {
    const int*   pairs;
    const float* emb;
    if (in_sizes[0] == 2 * BPAIRS) {         // pairs first (metadata order)
        pairs = (const int*)d_in[0];
        emb   = (const float*)d_in[1];
    } else {
        pairs = (const int*)d_in[1];
        emb   = (const float*)d_in[0];
    }
    float* out = (float*)d_out;

    k_init<<<(ROWS + 255) / 256, 256>>>();
    k_esq<<<(NODES + 7) / 8, 256>>>(emb);
    k_gather<<<ROWS / 8, 256>>>(pairs, emb);
    k_pos<<<BPAIRS / 8, 256>>>();

    dim3 gg(ROWS / BM, (NODES + BN - 1) / BN);   // 32 x 782
    k_gemm<<<gg, 256>>>(emb, pairs);

    dim3 g2(25, ROWS);                            // 25 chunks x 4096 rows
    k_pass2<<<g2, 256>>>();

    k_final<<<1, 1024>>>(out);
}

// round 7
// speedup vs baseline: 6.5875x; 6.5875x over previous
#include <cuda_runtime.h>
#include <cuda_bf16.h>
#include <math.h>
#include <stdint.h>

#define NODES  100000
#define NPAD   100096      // 782 * 128
#define DIM    512
#define BPAIRS 2048
#define ROWS   4096
#define GAMMA_ 3.0f
#define LAMB_  20.0f
#define TAU_   8.0f

#define BM 128
#define BN 128
#define BK 64              // bf16 k per chunk = 128 B/row (SW128 atom)
#define NCHUNK (DIM / BK)  // 8
#define STAGE_BYTES 32768  // 16K A + 16K B per stage

// ---------------- scratch ----------------------------------------------------
__device__ __nv_bfloat16 g_Ab[(size_t)ROWS * DIM];
__device__ __nv_bfloat16 g_Eb[(size_t)NPAD * DIM];    // pad rows stay zero
__device__ float g_asq[ROWS];
__device__ float g_pos[BPAIRS];
__device__ float g_esq[NODES];
__device__ float g_loss[(size_t)ROWS * NODES];        // 1.64 GB
__device__ float g_sum[ROWS], g_sumsq[ROWS], g_max[ROWS], g_sumexp[ROWS];

__device__ __forceinline__ void atomicMaxFloat(float* addr, float v) {
    int* ai = (int*)addr;
    int old = *ai;
    while (__int_as_float(old) < v) {
        int prev = atomicCAS(ai, old, __float_as_int(v));
        if (prev == old) break;
        old = prev;
    }
}

// ---------------- PTX helpers -------------------------------------------------
__device__ __forceinline__ uint32_t cvta_smem(const void* p) {
    uint32_t a;
    asm("{ .reg .u64 t; cvta.to.shared.u64 t, %1; cvt.u32.u64 %0, t; }" : "=r"(a) : "l"(p));
    return a;
}
__device__ __forceinline__ void cpasync16(uint32_t s, const void* g) {
    asm volatile("cp.async.cg.shared.global [%0], [%1], 16;" :: "r"(s), "l"(g));
}
__device__ __forceinline__ uint32_t swz(uint32_t off) {   // SW128: bits[6:4] ^= bits[9:7]
    return off ^ ((off >> 3) & 0x70);
}
__device__ __forceinline__ void ldsm_x4(uint32_t* r, uint32_t addr) {
    asm volatile("ldmatrix.sync.aligned.m8n8.x4.shared.b16 {%0,%1,%2,%3}, [%4];"
                 : "=r"(r[0]), "=r"(r[1]), "=r"(r[2]), "=r"(r[3]) : "r"(addr));
}
__device__ __forceinline__ void mma16816(float* c, const uint32_t* a, const uint32_t* b) {
    asm volatile(
        "mma.sync.aligned.m16n8k16.row.col.f32.bf16.bf16.f32 "
        "{%0,%1,%2,%3}, {%4,%5,%6,%7}, {%8,%9}, {%0,%1,%2,%3};"
        : "+f"(c[0]), "+f"(c[1]), "+f"(c[2]), "+f"(c[3])
        : "r"(a[0]), "r"(a[1]), "r"(a[2]), "r"(a[3]), "r"(b[0]), "r"(b[1]));
}

// ---------------- small kernels ----------------------------------------------
__global__ void k_init() {
    int i = blockIdx.x * blockDim.x + threadIdx.x;
    if (i < ROWS) {
        g_sum[i] = 0.f; g_sumsq[i] = 0.f; g_sumexp[i] = 0.f;
        g_max[i] = -INFINITY;
    }
}

// esq + bf16 convert of E, fused: one warp per node
__global__ void k_prepE(const float* __restrict__ emb) {
    int node = blockIdx.x * 8 + (threadIdx.x >> 5);
    if (node >= NODES) return;
    int lane = threadIdx.x & 31;
    const float4* p = (const float4*)(emb + (size_t)node * DIM);
    __nv_bfloat162* q = (__nv_bfloat162*)(g_Eb + (size_t)node * DIM);
    float s = 0.f;
    #pragma unroll
    for (int i = lane; i < DIM / 4; i += 32) {
        float4 v = p[i];
        s += v.x * v.x + v.y * v.y + v.z * v.z + v.w * v.w;
        q[i * 2 + 0] = __nv_bfloat162(__float2bfloat16_rn(v.x), __float2bfloat16_rn(v.y));
        q[i * 2 + 1] = __nv_bfloat162(__float2bfloat16_rn(v.z), __float2bfloat16_rn(v.w));
    }
    #pragma unroll
    for (int o = 16; o; o >>= 1) s += __shfl_xor_sync(0xffffffffu, s, o);
    if (lane == 0) g_esq[node] = s;
}

// gather A rows (bf16) + asq: one warp per row
__global__ void k_gather(const int* __restrict__ pairs, const float* __restrict__ emb) {
    int row = blockIdx.x * 8 + (threadIdx.x >> 5);
    if (row >= ROWS) return;
    int lane = threadIdx.x & 31;
    int p    = row & (BPAIRS - 1);
    int side = row >> 11;
    int node = pairs[2 * p + side];
    const float4* src = (const float4*)(emb + (size_t)node * DIM);
    __nv_bfloat162* dst = (__nv_bfloat162*)(g_Ab + (size_t)row * DIM);
    float s = 0.f;
    #pragma unroll
    for (int i = lane; i < DIM / 4; i += 32) {
        float4 v = src[i];
        s += v.x * v.x + v.y * v.y + v.z * v.z + v.w * v.w;
        dst[i * 2 + 0] = __nv_bfloat162(__float2bfloat16_rn(v.x), __float2bfloat16_rn(v.y));
        dst[i * 2 + 1] = __nv_bfloat162(__float2bfloat16_rn(v.z), __float2bfloat16_rn(v.w));
    }
    #pragma unroll
    for (int o = 16; o; o >>= 1) s += __shfl_xor_sync(0xffffffffu, s, o);
    if (lane == 0) g_asq[row] = s;
}

__global__ void k_pos(const int* __restrict__ pairs, const float* __restrict__ emb) {
    int p = blockIdx.x * 8 + (threadIdx.x >> 5);
    if (p >= BPAIRS) return;
    int lane = threadIdx.x & 31;
    int ln = pairs[2 * p], rn = pairs[2 * p + 1];
    const float4* a = (const float4*)(emb + (size_t)ln * DIM);
    const float4* b = (const float4*)(emb + (size_t)rn * DIM);
    float s = 0.f;
    #pragma unroll
    for (int i = lane; i < DIM / 4; i += 32) {
        float4 x = a[i], y = b[i];
        float dx = x.x - y.x, dy = x.y - y.y, dz = x.z - y.z, dw = x.w - y.w;
        s += dx * dx + dy * dy + dz * dz + dw * dw;
    }
    #pragma unroll
    for (int o = 16; o; o >>= 1) s += __shfl_xor_sync(0xffffffffu, s, o);
    if (lane == 0) g_pos[p] = s;
}

// ---------------- HMMA GEMM + loss + stats ------------------------------------
// dyn smem: 2 stages x (A 16K @0 | B 16K @16K) = 64 KB
__global__ void __launch_bounds__(256, 2) k_gemm_mma(const int* __restrict__ pairs) {
    extern __shared__ __align__(1024) char dsm[];
    __shared__ float s_esq[BN], s_asq[BM], s_pos[BM];
    __shared__ int   s_l[BM], s_r[BM];

    const int tid  = threadIdx.x;
    const int lane = tid & 31, w = tid >> 5;
    const int m0 = blockIdx.x * BM;
    const int n0 = blockIdx.y * BN;
    const uint32_t smb = cvta_smem(dsm);

    if (tid < BM) {
        int row = m0 + tid;
        s_asq[tid] = g_asq[row];
        int p = row & (BPAIRS - 1);
        s_pos[tid] = g_pos[p];
        s_l[tid] = pairs[2 * p];
        s_r[tid] = pairs[2 * p + 1];
        int col = n0 + tid;
        s_esq[tid] = (col < NODES) ? g_esq[col] : 0.f;
    }

    // warp tile: wm = (w>>1)*32 rows, wn = (w&1)*64 cols
    const int wm = (w >> 1) * 32;
    const int wn = (w & 1) * 64;

    // ldmatrix lane address components (unswizzled byte offsets, swz applied late)
    const uint32_t aRow  = (uint32_t)(lane & 15);          // + wm + mi*16
    const uint32_t aColB = (uint32_t)((lane >> 4) * 16);   // + kk*32
    const uint32_t grp   = (uint32_t)(lane >> 3);
    const uint32_t bRow  = (uint32_t)((lane & 7) + ((grp >> 1) * 8)); // + wn + nt2*16
    const uint32_t bColB = (uint32_t)((grp & 1) * 16);                // + kk*32

    float acc[2][8][4];
    #pragma unroll
    for (int mi = 0; mi < 2; mi++)
        #pragma unroll
        for (int ni = 0; ni < 8; ni++)
            #pragma unroll
            for (int q = 0; q < 4; q++) acc[mi][ni][q] = 0.f;

    // ---- async load of one chunk into stage st ----
    auto load_chunk = [&](int c, int st) {
        uint32_t sb = smb + (uint32_t)st * STAGE_BYTES;
        #pragma unroll
        for (int i = 0; i < 4; i++) {
            int idx = tid + 256 * i;                 // 1024 segs of 16B for A
            int r = idx >> 3, seg = idx & 7;
            const void* src = g_Ab + (size_t)(m0 + r) * DIM + c * BK + seg * 8;
            cpasync16(sb + swz((uint32_t)(r * 128 + seg * 16)), src);
        }
        #pragma unroll
        for (int i = 0; i < 4; i++) {
            int idx = tid + 256 * i;
            int r = idx >> 3, seg = idx & 7;
            const void* src = g_Eb + (size_t)(n0 + r) * DIM + c * BK + seg * 8;
            cpasync16(sb + 16384u + swz((uint32_t)(r * 128 + seg * 16)), src);
        }
        asm volatile("cp.async.commit_group;" ::: "memory");
    };

    load_chunk(0, 0);
    __syncthreads();   // covers s_* fills too

    for (int c = 0; c < NCHUNK; c++) {
        if (c < NCHUNK - 1) load_chunk(c + 1, (c + 1) & 1);
        if (c < NCHUNK - 1)
            asm volatile("cp.async.wait_group 1;" ::: "memory");
        else
            asm volatile("cp.async.wait_group 0;" ::: "memory");
        __syncthreads();

        uint32_t sA = smb + (uint32_t)(c & 1) * STAGE_BYTES;
        uint32_t sB = sA + 16384u;

        #pragma unroll
        for (int kk = 0; kk < 4; kk++) {
            uint32_t a[2][4];
            #pragma unroll
            for (int mi = 0; mi < 2; mi++)
                ldsm_x4(a[mi], sA + swz((uint32_t)((wm + mi * 16 + aRow) * 128 +
                                                   kk * 32 + aColB)));
            uint32_t b[4][4];
            #pragma unroll
            for (int nt = 0; nt < 4; nt++)
                ldsm_x4(b[nt], sB + swz((uint32_t)((wn + nt * 16 + bRow) * 128 +
                                                   kk * 32 + bColB)));
            #pragma unroll
            for (int mi = 0; mi < 2; mi++)
                #pragma unroll
                for (int nt = 0; nt < 4; nt++) {
                    mma16816(acc[mi][nt * 2 + 0], a[mi], &b[nt][0]);
                    mma16816(acc[mi][nt * 2 + 1], a[mi], &b[nt][2]);
                }
        }
        __syncthreads();   // stage reusable for load c+2
    }

    // ---- epilogue: loss + store + per-row stats ----
    const int qr = lane >> 2, qc = lane & 3;

    #pragma unroll
    for (int mi = 0; mi < 2; mi++) {
        #pragma unroll
        for (int h = 0; h < 2; h++) {
            int rl  = wm + mi * 16 + h * 8 + qr;     // tile-local row
            int row = m0 + rl;
            float asq = s_asq[rl], pos = s_pos[rl];
            int   li = s_l[rl], ri = s_r[rl];
            float base = pos + GAMMA_ - asq;
            float psum = 0.f, psq = 0.f, pmax = -INFINITY;
            #pragma unroll
            for (int ni = 0; ni < 8; ni++) {
                int tc0 = wn + ni * 8 + qc * 2;      // tile-local col (even)
                int col0 = n0 + tc0;
                float d0 = acc[mi][ni][h * 2 + 0];
                float d1 = acc[mi][ni][h * 2 + 1];
                float l0 = (base - s_esq[tc0]     + 2.f * d0);
                float l1 = (base - s_esq[tc0 + 1] + 2.f * d1);
                l0 *= 1.f - (float)(col0 == li)     - (float)(col0 == ri);
                l1 *= 1.f - (float)(col0 + 1 == li) - (float)(col0 + 1 == ri);
                if (col0 < NODES) {                  // NODES even -> pair valid
                    psum += l0 + l1;
                    psq  += l0 * l0 + l1 * l1;
                    pmax  = fmaxf(pmax, fmaxf(l0, l1));
                    *(float2*)(g_loss + (size_t)row * NODES + col0) =
                        make_float2(l0, l1);
                }
            }
            // reduce over the 4 qc lanes sharing this row
            #pragma unroll
            for (int o = 1; o < 4; o <<= 1) {
                psum += __shfl_xor_sync(0xffffffffu, psum, o);
                psq  += __shfl_xor_sync(0xffffffffu, psq, o);
                pmax  = fmaxf(pmax, __shfl_xor_sync(0xffffffffu, pmax, o));
            }
            if (qc == 0) {
                atomicAdd(&g_sum[row], psum);
                atomicAdd(&g_sumsq[row], psq);
                atomicMaxFloat(&g_max[row], pmax);
            }
        }
    }
}

// ---------------- pass 2 + finalize (verified) --------------------------------
__global__ void __launch_bounds__(256) k_pass2() {
    const int row = blockIdx.y;
    float mu  = g_sum[row] * (1.f / NODES);
    float var = g_sumsq[row] * (1.f / NODES) - mu * mu;
    float sd  = sqrtf(fmaxf(var, 0.f));
    float scale = LAMB_ / sd;
    float mx  = g_max[row];

    const float4* L = (const float4*)(g_loss + (size_t)row * NODES);
    int start = blockIdx.x * 1000;
    float s = 0.f;
    for (int j = start + threadIdx.x; j < start + 1000; j += 256) {
        float4 v = L[j];
        s += __expf(scale * (v.x - mx));
        s += __expf(scale * (v.y - mx));
        s += __expf(scale * (v.z - mx));
        s += __expf(scale * (v.w - mx));
    }
    __shared__ float red[8];
    int lane = threadIdx.x & 31, wd = threadIdx.x >> 5;
    #pragma unroll
    for (int o = 16; o; o >>= 1) s += __shfl_xor_sync(0xffffffffu, s, o);
    if (lane == 0) red[wd] = s;
    __syncthreads();
    if (threadIdx.x < 8) {
        float v = red[threadIdx.x];
        #pragma unroll
        for (int o = 4; o; o >>= 1) v += __shfl_xor_sync(0xffu, v, o);
        if (threadIdx.x == 0) atomicAdd(&g_sumexp[row], v);
    }
}

__global__ void k_final(float* __restrict__ out) {
    __shared__ float red[32];
    float t = 0.f;
    for (int row = threadIdx.x; row < ROWS; row += 1024) {
        float mu  = g_sum[row] * (1.f / NODES);
        float var = g_sumsq[row] * (1.f / NODES) - mu * mu;
        float sd  = sqrtf(fmaxf(var, 0.f));
        float lse = LAMB_ * (g_max[row] - mu) / sd + TAU_ + logf(g_sumexp[row]);
        t += lse;
    }
    int lane = threadIdx.x & 31, wd = threadIdx.x >> 5;
    #pragma unroll
    for (int o = 16; o; o >>= 1) t += __shfl_xor_sync(0xffffffffu, t, o);
    if (lane == 0) red[wd] = t;
    __syncthreads();
    if (threadIdx.x < 32) {
        float v = red[threadIdx.x];
        #pragma unroll
        for (int o = 16; o; o >>= 1) v += __shfl_xor_sync(0xffffffffu, v, o);
        if (threadIdx.x == 0) out[0] = v * (1.f / BPAIRS);
    }
}

// ---------------- launch ------------------------------------------------------
extern "C" void kernel_launch(void* const* d_in, const int* in_sizes, int n_in,
                              void* d_out, int out_size) {
    const int*   pairs;
    const float* emb;
    if (in_sizes[0] == 2 * BPAIRS) {
        pairs = (const int*)d_in[0];
        emb   = (const float*)d_in[1];
    } else {
        pairs = (const int*)d_in[1];
        emb   = (const float*)d_in[0];
    }
    float* out = (float*)d_out;

    cudaFuncSetAttribute(k_gemm_mma, cudaFuncAttributeMaxDynamicSharedMemorySize, 65536);

    k_init<<<(ROWS + 255) / 256, 256>>>();
    k_prepE<<<(NODES + 7) / 8, 256>>>(emb);
    k_gather<<<ROWS / 8, 256>>>(pairs, emb);
    k_pos<<<BPAIRS / 8, 256>>>(pairs, emb);

    dim3 gg(ROWS / BM, NPAD / BN);            // 32 x 782, x fastest -> E-tile L2 reuse
    k_gemm_mma<<<gg, 256, 65536>>>(pairs);

    dim3 g2(25, ROWS);
    k_pass2<<<g2, 256>>>();

    k_final<<<1, 1024>>>(out);
}

// round 8
// speedup vs baseline: 6.5885x; 1.0001x over previous
#include <cuda_runtime.h>
#include <cuda_bf16.h>
#include <math.h>
#include <stdint.h>

#define NODES  100000
#define NPAD   100096      // 782 * 128
#define DIM    512
#define BPAIRS 2048
#define ROWS   4096
#define GAMMA_ 3.0f
#define LAMB_  20.0f
#define TAU_   8.0f

#define BM 128
#define BN 128
#define BK 64              // bf16 k per chunk = 128 B/row (SW128 atom)
#define NCHUNK (DIM / BK)  // 8
#define STAGE_BYTES 32768  // 16K A + 16K B per stage

// ---------------- scratch ----------------------------------------------------
__device__ __nv_bfloat16 g_Ab[(size_t)ROWS * DIM];
__device__ __nv_bfloat16 g_Eb[(size_t)NPAD * DIM];    // pad rows stay zero
__device__ float g_asq[ROWS];
__device__ float g_pos[BPAIRS];
__device__ float g_esq[NODES];
__device__ float g_loss[(size_t)ROWS * NODES];        // 1.64 GB
__device__ float g_sum[ROWS], g_sumsq[ROWS], g_max[ROWS], g_sumexp[ROWS];

__device__ __forceinline__ void atomicMaxFloat(float* addr, float v) {
    int* ai = (int*)addr;
    int old = *ai;
    while (__int_as_float(old) < v) {
        int prev = atomicCAS(ai, old, __float_as_int(v));
        if (prev == old) break;
        old = prev;
    }
}

// ---------------- PTX helpers -------------------------------------------------
__device__ __forceinline__ uint32_t cvta_smem(const void* p) {
    uint32_t a;
    asm("{ .reg .u64 t; cvta.to.shared.u64 t, %1; cvt.u32.u64 %0, t; }" : "=r"(a) : "l"(p));
    return a;
}
__device__ __forceinline__ void cpasync16(uint32_t s, const void* g) {
    asm volatile("cp.async.cg.shared.global [%0], [%1], 16;" :: "r"(s), "l"(g));
}
__device__ __forceinline__ uint32_t swz(uint32_t off) {   // SW128: bits[6:4] ^= bits[9:7]
    return off ^ ((off >> 3) & 0x70);
}
__device__ __forceinline__ void ldsm_x4(uint32_t* r, uint32_t addr) {
    asm volatile("ldmatrix.sync.aligned.m8n8.x4.shared.b16 {%0,%1,%2,%3}, [%4];"
                 : "=r"(r[0]), "=r"(r[1]), "=r"(r[2]), "=r"(r[3]) : "r"(addr));
}
__device__ __forceinline__ void mma16816(float* c, const uint32_t* a, const uint32_t* b) {
    asm volatile(
        "mma.sync.aligned.m16n8k16.row.col.f32.bf16.bf16.f32 "
        "{%0,%1,%2,%3}, {%4,%5,%6,%7}, {%8,%9}, {%0,%1,%2,%3};"
        : "+f"(c[0]), "+f"(c[1]), "+f"(c[2]), "+f"(c[3])
        : "r"(a[0]), "r"(a[1]), "r"(a[2]), "r"(a[3]), "r"(b[0]), "r"(b[1]));
}

// ---------------- small kernels ----------------------------------------------
__global__ void k_init() {
    int i = blockIdx.x * blockDim.x + threadIdx.x;
    if (i < ROWS) {
        g_sum[i] = 0.f; g_sumsq[i] = 0.f; g_sumexp[i] = 0.f;
        g_max[i] = -INFINITY;
    }
}

// esq + bf16 convert of E, fused: one warp per node
__global__ void k_prepE(const float* __restrict__ emb) {
    int node = blockIdx.x * 8 + (threadIdx.x >> 5);
    if (node >= NODES) return;
    int lane = threadIdx.x & 31;
    const float4* p = (const float4*)(emb + (size_t)node * DIM);
    __nv_bfloat162* q = (__nv_bfloat162*)(g_Eb + (size_t)node * DIM);
    float s = 0.f;
    #pragma unroll
    for (int i = lane; i < DIM / 4; i += 32) {
        float4 v = p[i];
        s += v.x * v.x + v.y * v.y + v.z * v.z + v.w * v.w;
        q[i * 2 + 0] = __nv_bfloat162(__float2bfloat16_rn(v.x), __float2bfloat16_rn(v.y));
        q[i * 2 + 1] = __nv_bfloat162(__float2bfloat16_rn(v.z), __float2bfloat16_rn(v.w));
    }
    #pragma unroll
    for (int o = 16; o; o >>= 1) s += __shfl_xor_sync(0xffffffffu, s, o);
    if (lane == 0) g_esq[node] = s;
}

// gather A rows (bf16) + asq: one warp per row
__global__ void k_gather(const int* __restrict__ pairs, const float* __restrict__ emb) {
    int row = blockIdx.x * 8 + (threadIdx.x >> 5);
    if (row >= ROWS) return;
    int lane = threadIdx.x & 31;
    int p    = row & (BPAIRS - 1);
    int side = row >> 11;
    int node = pairs[2 * p + side];
    const float4* src = (const float4*)(emb + (size_t)node * DIM);
    __nv_bfloat162* dst = (__nv_bfloat162*)(g_Ab + (size_t)row * DIM);
    float s = 0.f;
    #pragma unroll
    for (int i = lane; i < DIM / 4; i += 32) {
        float4 v = src[i];
        s += v.x * v.x + v.y * v.y + v.z * v.z + v.w * v.w;
        dst[i * 2 + 0] = __nv_bfloat162(__float2bfloat16_rn(v.x), __float2bfloat16_rn(v.y));
        dst[i * 2 + 1] = __nv_bfloat162(__float2bfloat16_rn(v.z), __float2bfloat16_rn(v.w));
    }
    #pragma unroll
    for (int o = 16; o; o >>= 1) s += __shfl_xor_sync(0xffffffffu, s, o);
    if (lane == 0) g_asq[row] = s;
}

__global__ void k_pos(const int* __restrict__ pairs, const float* __restrict__ emb) {
    int p = blockIdx.x * 8 + (threadIdx.x >> 5);
    if (p >= BPAIRS) return;
    int lane = threadIdx.x & 31;
    int ln = pairs[2 * p], rn = pairs[2 * p + 1];
    const float4* a = (const float4*)(emb + (size_t)ln * DIM);
    const float4* b = (const float4*)(emb + (size_t)rn * DIM);
    float s = 0.f;
    #pragma unroll
    for (int i = lane; i < DIM / 4; i += 32) {
        float4 x = a[i], y = b[i];
        float dx = x.x - y.x, dy = x.y - y.y, dz = x.z - y.z, dw = x.w - y.w;
        s += dx * dx + dy * dy + dz * dz + dw * dw;
    }
    #pragma unroll
    for (int o = 16; o; o >>= 1) s += __shfl_xor_sync(0xffffffffu, s, o);
    if (lane == 0) g_pos[p] = s;
}

// ---------------- HMMA GEMM + loss + stats ------------------------------------
// dyn smem: 2 stages x (A 16K @0 | B 16K @16K) = 64 KB
__global__ void __launch_bounds__(256, 2) k_gemm_mma(const int* __restrict__ pairs) {
    extern __shared__ __align__(1024) char dsm[];
    __shared__ float s_esq[BN], s_asq[BM], s_pos[BM];
    __shared__ int   s_l[BM], s_r[BM];

    const int tid  = threadIdx.x;
    const int lane = tid & 31, w = tid >> 5;
    const int m0 = blockIdx.x * BM;
    const int n0 = blockIdx.y * BN;
    const uint32_t smb = cvta_smem(dsm);

    if (tid < BM) {
        int row = m0 + tid;
        s_asq[tid] = g_asq[row];
        int p = row & (BPAIRS - 1);
        s_pos[tid] = g_pos[p];
        s_l[tid] = pairs[2 * p];
        s_r[tid] = pairs[2 * p + 1];
        int col = n0 + tid;
        s_esq[tid] = (col < NODES) ? g_esq[col] : 0.f;
    }

    // warp tile: wm = (w>>1)*32 rows, wn = (w&1)*64 cols
    const int wm = (w >> 1) * 32;
    const int wn = (w & 1) * 64;

    // ldmatrix lane address components (unswizzled byte offsets, swz applied late)
    const uint32_t aRow  = (uint32_t)(lane & 15);          // + wm + mi*16
    const uint32_t aColB = (uint32_t)((lane >> 4) * 16);   // + kk*32
    const uint32_t grp   = (uint32_t)(lane >> 3);
    const uint32_t bRow  = (uint32_t)((lane & 7) + ((grp >> 1) * 8)); // + wn + nt2*16
    const uint32_t bColB = (uint32_t)((grp & 1) * 16);                // + kk*32

    float acc[2][8][4];
    #pragma unroll
    for (int mi = 0; mi < 2; mi++)
        #pragma unroll
        for (int ni = 0; ni < 8; ni++)
            #pragma unroll
            for (int q = 0; q < 4; q++) acc[mi][ni][q] = 0.f;

    // ---- async load of one chunk into stage st ----
    auto load_chunk = [&](int c, int st) {
        uint32_t sb = smb + (uint32_t)st * STAGE_BYTES;
        #pragma unroll
        for (int i = 0; i < 4; i++) {
            int idx = tid + 256 * i;                 // 1024 segs of 16B for A
            int r = idx >> 3, seg = idx & 7;
            const void* src = g_Ab + (size_t)(m0 + r) * DIM + c * BK + seg * 8;
            cpasync16(sb + swz((uint32_t)(r * 128 + seg * 16)), src);
        }
        #pragma unroll
        for (int i = 0; i < 4; i++) {
            int idx = tid + 256 * i;
            int r = idx >> 3, seg = idx & 7;
            const void* src = g_Eb + (size_t)(n0 + r) * DIM + c * BK + seg * 8;
            cpasync16(sb + 16384u + swz((uint32_t)(r * 128 + seg * 16)), src);
        }
        asm volatile("cp.async.commit_group;" ::: "memory");
    };

    load_chunk(0, 0);
    __syncthreads();   // covers s_* fills too

    for (int c = 0; c < NCHUNK; c++) {
        if (c < NCHUNK - 1) load_chunk(c + 1, (c + 1) & 1);
        if (c < NCHUNK - 1)
            asm volatile("cp.async.wait_group 1;" ::: "memory");
        else
            asm volatile("cp.async.wait_group 0;" ::: "memory");
        __syncthreads();

        uint32_t sA = smb + (uint32_t)(c & 1) * STAGE_BYTES;
        uint32_t sB = sA + 16384u;

        #pragma unroll
        for (int kk = 0; kk < 4; kk++) {
            uint32_t a[2][4];
            #pragma unroll
            for (int mi = 0; mi < 2; mi++)
                ldsm_x4(a[mi], sA + swz((uint32_t)((wm + mi * 16 + aRow) * 128 +
                                                   kk * 32 + aColB)));
            uint32_t b[4][4];
            #pragma unroll
            for (int nt = 0; nt < 4; nt++)
                ldsm_x4(b[nt], sB + swz((uint32_t)((wn + nt * 16 + bRow) * 128 +
                                                   kk * 32 + bColB)));
            #pragma unroll
            for (int mi = 0; mi < 2; mi++)
                #pragma unroll
                for (int nt = 0; nt < 4; nt++) {
                    mma16816(acc[mi][nt * 2 + 0], a[mi], &b[nt][0]);
                    mma16816(acc[mi][nt * 2 + 1], a[mi], &b[nt][2]);
                }
        }
        __syncthreads();   // stage reusable for load c+2
    }

    // ---- epilogue: loss + store + per-row stats ----
    const int qr = lane >> 2, qc = lane & 3;

    #pragma unroll
    for (int mi = 0; mi < 2; mi++) {
        #pragma unroll
        for (int h = 0; h < 2; h++) {
            int rl  = wm + mi * 16 + h * 8 + qr;     // tile-local row
            int row = m0 + rl;
            float asq = s_asq[rl], pos = s_pos[rl];
            int   li = s_l[rl], ri = s_r[rl];
            float base = pos + GAMMA_ - asq;
            float psum = 0.f, psq = 0.f, pmax = -INFINITY;
            #pragma unroll
            for (int ni = 0; ni < 8; ni++) {
                int tc0 = wn + ni * 8 + qc * 2;      // tile-local col (even)
                int col0 = n0 + tc0;
                float d0 = acc[mi][ni][h * 2 + 0];
                float d1 = acc[mi][ni][h * 2 + 1];
                float l0 = (base - s_esq[tc0]     + 2.f * d0);
                float l1 = (base - s_esq[tc0 + 1] + 2.f * d1);
                l0 *= 1.f - (float)(col0 == li)     - (float)(col0 == ri);
                l1 *= 1.f - (float)(col0 + 1 == li) - (float)(col0 + 1 == ri);
                if (col0 < NODES) {                  // NODES even -> pair valid
                    psum += l0 + l1;
                    psq  += l0 * l0 + l1 * l1;
                    pmax  = fmaxf(pmax, fmaxf(l0, l1));
                    *(float2*)(g_loss + (size_t)row * NODES + col0) =
                        make_float2(l0, l1);
                }
            }
            // reduce over the 4 qc lanes sharing this row
            #pragma unroll
            for (int o = 1; o < 4; o <<= 1) {
                psum += __shfl_xor_sync(0xffffffffu, psum, o);
                psq  += __shfl_xor_sync(0xffffffffu, psq, o);
                pmax  = fmaxf(pmax, __shfl_xor_sync(0xffffffffu, pmax, o));
            }
            if (qc == 0) {
                atomicAdd(&g_sum[row], psum);
                atomicAdd(&g_sumsq[row], psq);
                atomicMaxFloat(&g_max[row], pmax);
            }
        }
    }
}

// ---------------- pass 2 + finalize (verified) --------------------------------
__global__ void __launch_bounds__(256) k_pass2() {
    const int row = blockIdx.y;
    float mu  = g_sum[row] * (1.f / NODES);
    float var = g_sumsq[row] * (1.f / NODES) - mu * mu;
    float sd  = sqrtf(fmaxf(var, 0.f));
    float scale = LAMB_ / sd;
    float mx  = g_max[row];

    const float4* L = (const float4*)(g_loss + (size_t)row * NODES);
    int start = blockIdx.x * 1000;
    float s = 0.f;
    for (int j = start + threadIdx.x; j < start + 1000; j += 256) {
        float4 v = L[j];
        s += __expf(scale * (v.x - mx));
        s += __expf(scale * (v.y - mx));
        s += __expf(scale * (v.z - mx));
        s += __expf(scale * (v.w - mx));
    }
    __shared__ float red[8];
    int lane = threadIdx.x & 31, wd = threadIdx.x >> 5;
    #pragma unroll
    for (int o = 16; o; o >>= 1) s += __shfl_xor_sync(0xffffffffu, s, o);
    if (lane == 0) red[wd] = s;
    __syncthreads();
    if (threadIdx.x < 8) {
        float v = red[threadIdx.x];
        #pragma unroll
        for (int o = 4; o; o >>= 1) v += __shfl_xor_sync(0xffu, v, o);
        if (threadIdx.x == 0) atomicAdd(&g_sumexp[row], v);
    }
}

__global__ void k_final(float* __restrict__ out) {
    __shared__ float red[32];
    float t = 0.f;
    for (int row = threadIdx.x; row < ROWS; row += 1024) {
        float mu  = g_sum[row] * (1.f / NODES);
        float var = g_sumsq[row] * (1.f / NODES) - mu * mu;
        float sd  = sqrtf(fmaxf(var, 0.f));
        float lse = LAMB_ * (g_max[row] - mu) / sd + TAU_ + logf(g_sumexp[row]);
        t += lse;
    }
    int lane = threadIdx.x & 31, wd = threadIdx.x >> 5;
    #pragma unroll
    for (int o = 16; o; o >>= 1) t += __shfl_xor_sync(0xffffffffu, t, o);
    if (lane == 0) red[wd] = t;
    __syncthreads();
    if (threadIdx.x < 32) {
        float v = red[threadIdx.x];
        #pragma unroll
        for (int o = 16; o; o >>= 1) v += __shfl_xor_sync(0xffffffffu, v, o);
        if (threadIdx.x == 0) out[0] = v * (1.f / BPAIRS);
    }
}

// ---------------- launch ------------------------------------------------------
extern "C" void kernel_launch(void* const* d_in, const int* in_sizes, int n_in,
                              void* d_out, int out_size) {
    const int*   pairs;
    const float* emb;
    if (in_sizes[0] == 2 * BPAIRS) {
        pairs = (const int*)d_in[0];
        emb   = (const float*)d_in[1];
    } else {
        pairs = (const int*)d_in[1];
        emb   = (const float*)d_in[0];
    }
    float* out = (float*)d_out;

    cudaFuncSetAttribute(k_gemm_mma, cudaFuncAttributeMaxDynamicSharedMemorySize, 65536);

    k_init<<<(ROWS + 255) / 256, 256>>>();
    k_prepE<<<(NODES + 7) / 8, 256>>>(emb);
    k_gather<<<ROWS / 8, 256>>>(pairs, emb);
    k_pos<<<BPAIRS / 8, 256>>>(pairs, emb);

    dim3 gg(ROWS / BM, NPAD / BN);            // 32 x 782, x fastest -> E-tile L2 reuse
    k_gemm_mma<<<gg, 256, 65536>>>(pairs);

    dim3 g2(25, ROWS);
    k_pass2<<<g2, 256>>>();

    k_final<<<1, 1024>>>(out);
}